// round 2
// baseline (speedup 1.0000x reference)
#include <cuda_runtime.h>
#include <math.h>

#define BB    2048
#define REPRK 8192
#define LOWD  32
#define FF    256
#define HH    512
#define SS    24
#define DD    8
#define NBINS 16
#define SBH   384   // S*BINS

// ---------------- scratch (device globals; no allocation allowed) ----------
__device__ float g_Wrgb[REPRK * 512];          // 16 MB  concat [v_W_rgb | q_W_rgb]
__device__ float g_rgb_pre[BB * 512];          // 4 MB   pre-LN rgb features (v|q)
__device__ float g_xv[BB * HH];                // [h1v | h2v]
__device__ float g_xq[BB * HH];                // [h1q | h2q]
__device__ float g_act[BB * SS * DD];          // actions
__device__ float g_t0[BB * HH];                // v-path pre buffer
__device__ float g_t1[BB * HH];                // v-path act buffer
__device__ float g_qbase[BB * HH];             // [h1q|h2q] @ q_W1[:512,:]
__device__ float g_q1[(size_t)BB * SS * HH];   // 100 MB
__device__ float g_q2pre[(size_t)BB * SS * HH];// 100 MB
__device__ float g_q2[(size_t)BB * SS * HH];   // 100 MB

// ---------------- block reduce (256 threads) -------------------------------
__device__ __forceinline__ float2 blockReduce2_256(float2 v) {
    __shared__ float2 sm[8];
    int lane = threadIdx.x & 31, w = threadIdx.x >> 5;
    #pragma unroll
    for (int o = 16; o > 0; o >>= 1) {
        v.x += __shfl_xor_sync(0xffffffffu, v.x, o);
        v.y += __shfl_xor_sync(0xffffffffu, v.y, o);
    }
    if (lane == 0) sm[w] = v;
    __syncthreads();
    if (threadIdx.x == 0) {
        float2 t = sm[0];
        #pragma unroll
        for (int i = 1; i < 8; i++) { t.x += sm[i].x; t.y += sm[i].y; }
        sm[0] = t;
    }
    __syncthreads();
    float2 r = sm[0];
    __syncthreads();
    return r;
}

// ---------------- generic fp32 tiled GEMM: C = A(MxK) @ W(KxN) --------------
// grid(N/64, M/64), 256 threads. Requires M%64==0, N%64==0, K%16==0.
__global__ void gemm_tile64(const float* __restrict__ A, const float* __restrict__ W,
                            float* __restrict__ C, int M, int N, int K) {
    __shared__ float As[16][68];   // [k][m], padded
    __shared__ float Ws[16][64];   // [k][n]
    const int tid = threadIdx.x;
    const int tx = tid & 15, ty = tid >> 4;
    const int m0 = blockIdx.y * 64, n0 = blockIdx.x * 64;
    const int a_row = tid >> 2;            // 0..63
    const int a_k   = (tid & 3) * 4;       // 0,4,8,12
    const int w_k   = tid >> 4;            // 0..15
    const int w_n   = (tid & 15) * 4;      // 0..60

    float acc[4][4] = {};
    for (int k0 = 0; k0 < K; k0 += 16) {
        float4 av = *(const float4*)&A[(size_t)(m0 + a_row) * K + k0 + a_k];
        As[a_k + 0][a_row] = av.x;
        As[a_k + 1][a_row] = av.y;
        As[a_k + 2][a_row] = av.z;
        As[a_k + 3][a_row] = av.w;
        *(float4*)&Ws[w_k][w_n] = *(const float4*)&W[(size_t)(k0 + w_k) * N + n0 + w_n];
        __syncthreads();
        #pragma unroll
        for (int kk = 0; kk < 16; kk++) {
            float4 ra = *(const float4*)&As[kk][ty * 4];
            float4 rb = *(const float4*)&Ws[kk][tx * 4];
            acc[0][0] += ra.x * rb.x; acc[0][1] += ra.x * rb.y; acc[0][2] += ra.x * rb.z; acc[0][3] += ra.x * rb.w;
            acc[1][0] += ra.y * rb.x; acc[1][1] += ra.y * rb.y; acc[1][2] += ra.y * rb.z; acc[1][3] += ra.y * rb.w;
            acc[2][0] += ra.z * rb.x; acc[2][1] += ra.z * rb.y; acc[2][2] += ra.z * rb.z; acc[2][3] += ra.z * rb.w;
            acc[3][0] += ra.w * rb.x; acc[3][1] += ra.w * rb.y; acc[3][2] += ra.w * rb.z; acc[3][3] += ra.w * rb.w;
        }
        __syncthreads();
    }
    #pragma unroll
    for (int i = 0; i < 4; i++) {
        #pragma unroll
        for (int j = 0; j < 4; j++) {
            C[(size_t)(m0 + ty * 4 + i) * N + n0 + tx * 4 + j] = acc[i][j];
        }
    }
}

// ---------------- concat [v_W_rgb | q_W_rgb] -> g_Wrgb ----------------------
__global__ void concat_wrgb(const float* __restrict__ vW, const float* __restrict__ qW,
                            float* __restrict__ out) {
    int i = blockIdx.x * blockDim.x + threadIdx.x;
    if (i >= REPRK * 512) return;
    int k = i >> 9, j = i & 511;
    out[i] = (j < 256) ? vW[k * 256 + j] : qW[k * 256 + (j - 256)];
}

// ---------------- LN(256) + tanh over rgb halves ----------------------------
// grid(B, 2): y==0 -> v half (cols 0..255), y==1 -> q half (cols 256..511)
__global__ void ln_tanh_rgb(const float* __restrict__ pre,
                            const float* __restrict__ vg, const float* __restrict__ vb,
                            const float* __restrict__ qg, const float* __restrict__ qb,
                            float* __restrict__ xv, float* __restrict__ xq) {
    int b = blockIdx.x, h = blockIdx.y, j = threadIdx.x;
    float x = pre[(size_t)b * 512 + h * 256 + j];
    float2 r = blockReduce2_256(make_float2(x, x * x));
    float mu = r.x * (1.f / 256.f);
    float var = r.y * (1.f / 256.f) - mu * mu;
    float inv = rsqrtf(var + 1e-5f);
    const float* g  = h ? qg : vg;
    const float* bb = h ? qb : vb;
    float y = tanhf((x - mu) * inv * g[j] + bb[j]);
    float* dst = h ? xq : xv;
    dst[(size_t)b * 512 + j] = y;
}

// ---------------- low GEMM (K=32) + LN(256) + tanh, both v and q ------------
__global__ void low_kernel(const float* __restrict__ low,
                           const float* __restrict__ vW, const float* __restrict__ vg, const float* __restrict__ vb,
                           const float* __restrict__ qW, const float* __restrict__ qg, const float* __restrict__ qb,
                           float* __restrict__ xv, float* __restrict__ xq) {
    int b = blockIdx.x, j = threadIdx.x;   // 256 threads
    __shared__ float lo[32];
    if (j < 32) lo[j] = low[b * 32 + j];
    __syncthreads();
    float sv = 0.f, sq = 0.f;
    #pragma unroll 8
    for (int k = 0; k < 32; k++) {
        float l = lo[k];
        sv += l * vW[k * 256 + j];
        sq += l * qW[k * 256 + j];
    }
    float2 rv = blockReduce2_256(make_float2(sv, sv * sv));
    float muv = rv.x * (1.f / 256.f);
    float iv  = rsqrtf(rv.y * (1.f / 256.f) - muv * muv + 1e-5f);
    xv[(size_t)b * 512 + 256 + j] = tanhf((sv - muv) * iv * vg[j] + vb[j]);
    float2 rq = blockReduce2_256(make_float2(sq, sq * sq));
    float muq = rq.x * (1.f / 256.f);
    float iq  = rsqrtf(rq.y * (1.f / 256.f) - muq * muq + 1e-5f);
    xq[(size_t)b * 512 + 256 + j] = tanhf((sq - muq) * iq * qg[j] + qb[j]);
}

// ---------------- actions from category -------------------------------------
__global__ void act_kernel(const int* __restrict__ cat, float* __restrict__ act) {
    int b = blockIdx.x * blockDim.x + threadIdx.x;
    if (b >= BB) return;
    float mids[3][8];
    #pragma unroll
    for (int d = 0; d < 8; d++) {
        float lowv = -1.f, width = 2.f;
        #pragma unroll
        for (int l = 0; l < 3; l++) {
            float w = width * (1.f / 16.f);
            float c = (float)cat[(b * 3 + l) * 8 + d];
            float nl = lowv + c * w;
            mids[l][d] = nl + 0.5f * w;
            lowv = nl; width = w;
        }
    }
    #pragma unroll
    for (int k = 0; k < 24; k++) {
        int ls = k >> 3, ds = k & 7;
        #pragma unroll
        for (int d = 0; d < 8; d++) {
            int lvl = ls + (d < ds ? 1 : 0);
            act[((size_t)b * 24 + k) * 8 + d] = (lvl == 0) ? 0.f : mids[lvl - 1][d];
        }
    }
}

// ---------------- LN(512) + SiLU, one row per block (256 thr, 2 elems) ------
__global__ void ln_silu_512(const float* __restrict__ pre, const float* __restrict__ g,
                            const float* __restrict__ bb, float* __restrict__ out) {
    size_t row = blockIdx.x;
    int j = threadIdx.x;
    float x0 = pre[row * 512 + j];
    float x1 = pre[row * 512 + 256 + j];
    float2 r = blockReduce2_256(make_float2(x0 + x1, x0 * x0 + x1 * x1));
    float mu = r.x * (1.f / 512.f);
    float inv = rsqrtf(r.y * (1.f / 512.f) - mu * mu + 1e-5f);
    float z0 = (x0 - mu) * inv * g[j] + bb[j];
    float z1 = (x1 - mu) * inv * g[j + 256] + bb[j + 256];
    out[row * 512 + j]       = z0 / (1.f + expf(-z0));
    out[row * 512 + 256 + j] = z1 / (1.f + expf(-z1));
}

// ---------------- q layer1: base + rank-8 action term + LN + SiLU -----------
__global__ void q1_kernel(const float* __restrict__ qbase, const float* __restrict__ act,
                          const float* __restrict__ qW1, const float* __restrict__ g,
                          const float* __restrict__ bb, float* __restrict__ out) {
    size_t idx = blockIdx.x;           // b*24 + s
    int b = (int)(idx / 24);
    int j = threadIdx.x;
    __shared__ float a[8];
    if (j < 8) a[j] = act[idx * 8 + j];
    __syncthreads();
    float x0 = qbase[(size_t)b * 512 + j];
    float x1 = qbase[(size_t)b * 512 + 256 + j];
    #pragma unroll
    for (int d = 0; d < 8; d++) {
        float av = a[d];
        x0 += av * qW1[(size_t)(512 + d) * 512 + j];
        x1 += av * qW1[(size_t)(512 + d) * 512 + 256 + j];
    }
    float2 r = blockReduce2_256(make_float2(x0 + x1, x0 * x0 + x1 * x1));
    float mu = r.x * (1.f / 512.f);
    float inv = rsqrtf(r.y * (1.f / 512.f) - mu * mu + 1e-5f);
    float z0 = (x0 - mu) * inv * g[j] + bb[j];
    float z1 = (x1 - mu) * inv * g[j + 256] + bb[j + 256];
    out[idx * 512 + j]       = z0 / (1.f + expf(-z0));
    out[idx * 512 + 256 + j] = z1 / (1.f + expf(-z1));
}

// ---------------- value head -------------------------------------------------
__global__ void vhead(const float* __restrict__ v2, const float* __restrict__ Wh,
                      const float* __restrict__ bh, float* __restrict__ out) {
    int b = blockIdx.x, j = threadIdx.x;
    float s = v2[(size_t)b * 512 + j] * Wh[j] + v2[(size_t)b * 512 + 256 + j] * Wh[256 + j];
    float2 r = blockReduce2_256(make_float2(s, 0.f));
    if (j == 0) out[b] = r.x + bh[0];
}

// ---------------- q head: diagonal-only (cols s*16..s*16+16) -----------------
// grid(B/64, S), 256 threads. Thread: row=tid>>2 (0..63), colgroup=tid&3 (4 cols)
__global__ void qhead(const float* __restrict__ A, const float* __restrict__ Wh,
                      const float* __restrict__ bh, float* __restrict__ out) {
    __shared__ float Ws[512][16];
    int s = blockIdx.y, mb = blockIdx.x, t = threadIdx.x;
    #pragma unroll
    for (int i = 0; i < 32; i++) {
        int idx = t + i * 256;
        int k = idx >> 4, v = idx & 15;
        Ws[k][v] = Wh[(size_t)k * SBH + s * 16 + v];
    }
    __syncthreads();
    int r = t >> 2, cg = t & 3;
    int b = mb * 64 + r;
    const float4* Ap = (const float4*)(A + ((size_t)b * 24 + s) * 512);
    float acc0 = 0.f, acc1 = 0.f, acc2 = 0.f, acc3 = 0.f;
    #pragma unroll 4
    for (int k4 = 0; k4 < 128; k4++) {
        float4 a = Ap[k4];
        int k = k4 * 4;
        float4 w;
        w = *(const float4*)&Ws[k + 0][cg * 4];
        acc0 += a.x * w.x; acc1 += a.x * w.y; acc2 += a.x * w.z; acc3 += a.x * w.w;
        w = *(const float4*)&Ws[k + 1][cg * 4];
        acc0 += a.y * w.x; acc1 += a.y * w.y; acc2 += a.y * w.z; acc3 += a.y * w.w;
        w = *(const float4*)&Ws[k + 2][cg * 4];
        acc0 += a.z * w.x; acc1 += a.z * w.y; acc2 += a.z * w.z; acc3 += a.z * w.w;
        w = *(const float4*)&Ws[k + 3][cg * 4];
        acc0 += a.w * w.x; acc1 += a.w * w.y; acc2 += a.w * w.z; acc3 += a.w * w.w;
    }
    size_t o = (size_t)b * SBH + s * 16 + cg * 4;
    int c0 = s * 16 + cg * 4;
    out[o + 0] = acc0 + bh[c0 + 0];
    out[o + 1] = acc1 + bh[c0 + 1];
    out[o + 2] = acc2 + bh[c0 + 2];
    out[o + 3] = acc3 + bh[c0 + 3];
}

// ---------------- launch ------------------------------------------------------
extern "C" void kernel_launch(void* const* d_in, const int* in_sizes, int n_in,
                              void* d_out, int out_size) {
    const float* rgb_obs = (const float*)d_in[0];
    const float* low_obs = (const float*)d_in[1];
    const int*   category = (const int*)d_in[2];
    const float* v_W_rgb = (const float*)d_in[3];
    const float* v_g_rgb = (const float*)d_in[4];
    const float* v_b_rgb = (const float*)d_in[5];
    const float* v_W_low = (const float*)d_in[6];
    const float* v_g_low = (const float*)d_in[7];
    const float* v_b_low = (const float*)d_in[8];
    const float* v_W1 = (const float*)d_in[9];
    const float* v_g1 = (const float*)d_in[10];
    const float* v_b1 = (const float*)d_in[11];
    const float* v_W2 = (const float*)d_in[12];
    const float* v_g2 = (const float*)d_in[13];
    const float* v_b2 = (const float*)d_in[14];
    const float* v_Wh = (const float*)d_in[15];
    const float* v_bh = (const float*)d_in[16];
    const float* q_W_rgb = (const float*)d_in[17];
    const float* q_g_rgb = (const float*)d_in[18];
    const float* q_b_rgb = (const float*)d_in[19];
    const float* q_W_low = (const float*)d_in[20];
    const float* q_g_low = (const float*)d_in[21];
    const float* q_b_low = (const float*)d_in[22];
    const float* q_W1 = (const float*)d_in[23];
    const float* q_g1 = (const float*)d_in[24];
    const float* q_b1 = (const float*)d_in[25];
    const float* q_W2 = (const float*)d_in[26];
    const float* q_g2 = (const float*)d_in[27];
    const float* q_b2 = (const float*)d_in[28];
    const float* q_Wh = (const float*)d_in[29];
    const float* q_bh = (const float*)d_in[30];

    float* out_value = (float*)d_out;          // [B]
    float* out_adv   = out_value + BB;         // [B, 384]

    float *Wrgb, *rgb_pre, *xv, *xq, *act, *t0, *t1, *qbase, *q1, *q2pre, *q2;
    cudaGetSymbolAddress((void**)&Wrgb,   g_Wrgb);
    cudaGetSymbolAddress((void**)&rgb_pre,g_rgb_pre);
    cudaGetSymbolAddress((void**)&xv,     g_xv);
    cudaGetSymbolAddress((void**)&xq,     g_xq);
    cudaGetSymbolAddress((void**)&act,    g_act);
    cudaGetSymbolAddress((void**)&t0,     g_t0);
    cudaGetSymbolAddress((void**)&t1,     g_t1);
    cudaGetSymbolAddress((void**)&qbase,  g_qbase);
    cudaGetSymbolAddress((void**)&q1,     g_q1);
    cudaGetSymbolAddress((void**)&q2pre,  g_q2pre);
    cudaGetSymbolAddress((void**)&q2,     g_q2);

    // Stage 0: weight concat + shared feature extraction
    concat_wrgb<<<(REPRK * 512 + 255) / 256, 256>>>(v_W_rgb, q_W_rgb, Wrgb);
    gemm_tile64<<<dim3(512 / 64, BB / 64), 256>>>(rgb_obs, Wrgb, rgb_pre, BB, 512, REPRK);
    ln_tanh_rgb<<<dim3(BB, 2), 256>>>(rgb_pre, v_g_rgb, v_b_rgb, q_g_rgb, q_b_rgb, xv, xq);
    low_kernel<<<BB, 256>>>(low_obs, v_W_low, v_g_low, v_b_low,
                            q_W_low, q_g_low, q_b_low, xv, xq);
    act_kernel<<<(BB + 127) / 128, 128>>>(category, act);

    // Value path
    gemm_tile64<<<dim3(8, BB / 64), 256>>>(xv, v_W1, t0, BB, 512, 512);
    ln_silu_512<<<BB, 256>>>(t0, v_g1, v_b1, t1);
    gemm_tile64<<<dim3(8, BB / 64), 256>>>(t1, v_W2, t0, BB, 512, 512);
    ln_silu_512<<<BB, 256>>>(t0, v_g2, v_b2, t1);
    vhead<<<BB, 256>>>(t1, v_Wh, v_bh, out_value);

    // Q path
    gemm_tile64<<<dim3(8, BB / 64), 256>>>(xq, q_W1, qbase, BB, 512, 512);  // rows 0..511 of q_W1
    q1_kernel<<<BB * SS, 256>>>(qbase, act, q_W1, q_g1, q_b1, q1);
    gemm_tile64<<<dim3(8, (BB * SS) / 64), 256>>>(q1, q_W2, q2pre, BB * SS, 512, 512);
    ln_silu_512<<<BB * SS, 256>>>(q2pre, q_g2, q_b2, q2);
    qhead<<<dim3(BB / 64, SS), 256>>>(q2, q_Wh, q_bh, out_adv);
}

// round 4
// speedup vs baseline: 2.0977x; 2.0977x over previous
#include <cuda_runtime.h>
#include <cuda_bf16.h>
#include <stdint.h>
#include <math.h>

#define BB    2048
#define REPRK 8192
#define FF    256
#define HH    512
#define SS    24
#define DD    8
#define SBH   384   // S*BINS

// ===================== PTX helpers (non-arch-specific) ======================
__device__ __forceinline__ uint32_t smem_u32(const void* p) {
    uint32_t a;
    asm("{ .reg .u64 t; cvta.to.shared.u64 t, %1; cvt.u32.u64 %0, t; }" : "=r"(a) : "l"(p));
    return a;
}
__device__ __forceinline__ void cp16(uint32_t saddr, const void* g) {
    asm volatile("cp.async.cg.shared.global [%0], [%1], 16;" :: "r"(saddr), "l"(g));
}
#define CPCOMMIT asm volatile("cp.async.commit_group;" ::: "memory")
#define CPWAIT1  asm volatile("cp.async.wait_group 1;" ::: "memory")

__device__ __forceinline__ void ldsm4(uint32_t* r, uint32_t addr) {
    asm volatile("ldmatrix.sync.aligned.m8n8.x4.shared.b16 {%0,%1,%2,%3}, [%4];"
        : "=r"(r[0]), "=r"(r[1]), "=r"(r[2]), "=r"(r[3]) : "r"(addr));
}
__device__ __forceinline__ void mma_bf16(float* d, const uint32_t* a, uint32_t b0, uint32_t b1) {
    asm volatile("mma.sync.aligned.m16n8k16.row.col.f32.bf16.bf16.f32 "
        "{%0,%1,%2,%3}, {%4,%5,%6,%7}, {%8,%9}, {%0,%1,%2,%3};"
        : "+f"(d[0]), "+f"(d[1]), "+f"(d[2]), "+f"(d[3])
        : "r"(a[0]), "r"(a[1]), "r"(a[2]), "r"(a[3]), "r"(b0), "r"(b1));
}

// ===================== scratch (device globals) =============================
__device__ __nv_bfloat16 g_Ahi[(size_t)BB * REPRK];       // 32 MB
__device__ __nv_bfloat16 g_Alo[(size_t)BB * REPRK];
__device__ __nv_bfloat16 g_WrgbTh[(size_t)512 * REPRK];   // 8 MB
__device__ __nv_bfloat16 g_WrgbTl[(size_t)512 * REPRK];
__device__ float g_rgb_part[4 * BB * 512];                // 16 MB split-K partials
__device__ float g_rgb_pre[BB * 512];
__device__ __nv_bfloat16 g_xvh[BB * 512], g_xvl[BB * 512];
__device__ __nv_bfloat16 g_xqh[BB * 512], g_xql[BB * 512];
__device__ __nv_bfloat16 g_vW1Th[512 * 512], g_vW1Tl[512 * 512];
__device__ __nv_bfloat16 g_vW2Th[512 * 512], g_vW2Tl[512 * 512];
__device__ __nv_bfloat16 g_qW1Th[512 * 512], g_qW1Tl[512 * 512];
__device__ __nv_bfloat16 g_qW2Th[512 * 512], g_qW2Tl[512 * 512];
__device__ float g_t0[BB * 512];
__device__ __nv_bfloat16 g_t1h[BB * 512], g_t1l[BB * 512];
__device__ float g_t1f[BB * 512];
__device__ float g_qbase[BB * 512];
__device__ float g_act[BB * SS * DD];
__device__ __nv_bfloat16 g_q1h[(size_t)BB * SS * 512];    // 50 MB
__device__ __nv_bfloat16 g_q1l[(size_t)BB * SS * 512];
__device__ float g_q2pre[(size_t)BB * SS * 512];          // 100 MB
__device__ float g_q2f[(size_t)BB * SS * 512];            // 100 MB

// ===================== small helpers ========================================
__device__ __forceinline__ void split_bf16(float x, __nv_bfloat16& h, __nv_bfloat16& l) {
    h = __float2bfloat16_rn(x);
    l = __float2bfloat16_rn(x - __bfloat162float(h));
}

__device__ __forceinline__ float2 blockReduce2_256(float2 v) {
    __shared__ float2 sm[8];
    int lane = threadIdx.x & 31, w = threadIdx.x >> 5;
    #pragma unroll
    for (int o = 16; o > 0; o >>= 1) {
        v.x += __shfl_xor_sync(0xffffffffu, v.x, o);
        v.y += __shfl_xor_sync(0xffffffffu, v.y, o);
    }
    if (lane == 0) sm[w] = v;
    __syncthreads();
    if (threadIdx.x == 0) {
        float2 t = sm[0];
        #pragma unroll
        for (int i = 1; i < 8; i++) { t.x += sm[i].x; t.y += sm[i].y; }
        sm[0] = t;
    }
    __syncthreads();
    float2 r = sm[0];
    __syncthreads();
    return r;
}

// ===================== HMMA 3-pass bf16 GEMM ================================
// C(MxN, f32, at z-slice offset) = Ahi*Bhi^T + Ahi*Blo^T + Alo*Bhi^T
// A[M][lda], B[N][lda] bf16 row-major (K contiguous). Tile 128x128x32.
// grid(N/128, M/128, nz); 512 threads; 64KB dynamic smem (2 stages x 32KB).
__global__ __launch_bounds__(512, 1)
void gemm_mma3(const __nv_bfloat16* __restrict__ Ah, const __nv_bfloat16* __restrict__ Al,
               const __nv_bfloat16* __restrict__ Bh, const __nv_bfloat16* __restrict__ Bl,
               float* __restrict__ C, int M, int N, int Kslice, int lda) {
    extern __shared__ char smdyn[];
    const int tid = threadIdx.x;
    const int lane = tid & 31, wid = tid >> 5;
    const int wm = wid & 3, wn = wid >> 2;       // 4x4 warp grid
    const int m0 = blockIdx.y * 128, n0 = blockIdx.x * 128;
    const size_t kbase = (size_t)blockIdx.z * Kslice;
    float* Cz = C + (size_t)blockIdx.z * M * N;

    // loader coords: 512 threads x 1 chunk(16B) per buffer
    const int lrow = tid >> 2, lc = tid & 3;
    const int lpc = lc ^ ((lrow >> 1) & 3);
    const uint32_t sb0 = smem_u32(smdyn);
    const uint32_t s_store = sb0 + lrow * 64 + lpc * 16;
    const __nv_bfloat16* gAh = Ah + (size_t)(m0 + lrow) * lda + kbase + lc * 8;
    const __nv_bfloat16* gAl = Al + (size_t)(m0 + lrow) * lda + kbase + lc * 8;
    const __nv_bfloat16* gBh = Bh + (size_t)(n0 + lrow) * lda + kbase + lc * 8;
    const __nv_bfloat16* gBl = Bl + (size_t)(n0 + lrow) * lda + kbase + lc * 8;

    const int nch = Kslice >> 5;

#define LOADST(s, i) do { \
    uint32_t _so = s_store + (uint32_t)(s) * 32768u; \
    size_t _ko = (size_t)(i) * 32; \
    cp16(_so,          gAh + _ko); \
    cp16(_so +  8192,  gAl + _ko); \
    cp16(_so + 16384,  gBh + _ko); \
    cp16(_so + 24576,  gBl + _ko); } while (0)

    LOADST(0, 0); CPCOMMIT;
    LOADST(1, 1); CPCOMMIT;

    float acc[2][4][4];
    #pragma unroll
    for (int mf = 0; mf < 2; mf++)
        #pragma unroll
        for (int nf = 0; nf < 4; nf++)
            #pragma unroll
            for (int r = 0; r < 4; r++) acc[mf][nf][r] = 0.f;

    const int r15 = lane & 15, ksel = lane >> 4;

    for (int i = 0; i < nch; i++) {
        CPWAIT1;
        __syncthreads();
        uint32_t sb = sb0 + (uint32_t)(i & 1) * 32768u;
        #pragma unroll
        for (int kt = 0; kt < 2; kt++) {
            const int cA = 2 * kt + ksel;
            uint32_t a[2][4], al[2][4], bh[2][4], bl[2][4];
            #pragma unroll
            for (int mf = 0; mf < 2; mf++) {
                int row = wm * 32 + mf * 16 + r15;
                uint32_t off = (uint32_t)(row * 64 + ((cA ^ ((row >> 1) & 3)) * 16));
                ldsm4(a[mf], sb + off);
            }
            #pragma unroll
            for (int nf2 = 0; nf2 < 2; nf2++) {
                int row = wn * 32 + nf2 * 16 + r15;
                uint32_t off = (uint32_t)(row * 64 + ((cA ^ ((row >> 1) & 3)) * 16));
                ldsm4(bh[nf2], sb + 16384 + off);
                ldsm4(bl[nf2], sb + 24576 + off);
            }
            // pass 1: Ahi * Bhi ; pass 2: Ahi * Blo
            #pragma unroll
            for (int mf = 0; mf < 2; mf++)
                #pragma unroll
                for (int nf = 0; nf < 4; nf++) {
                    mma_bf16(acc[mf][nf], a[mf], bh[nf >> 1][nf & 1], bh[nf >> 1][2 + (nf & 1)]);
                    mma_bf16(acc[mf][nf], a[mf], bl[nf >> 1][nf & 1], bl[nf >> 1][2 + (nf & 1)]);
                }
            // pass 3: Alo * Bhi
            #pragma unroll
            for (int mf = 0; mf < 2; mf++) {
                int row = wm * 32 + mf * 16 + r15;
                uint32_t off = (uint32_t)(row * 64 + ((cA ^ ((row >> 1) & 3)) * 16));
                ldsm4(al[mf], sb + 8192 + off);
            }
            #pragma unroll
            for (int mf = 0; mf < 2; mf++)
                #pragma unroll
                for (int nf = 0; nf < 4; nf++)
                    mma_bf16(acc[mf][nf], al[mf], bh[nf >> 1][nf & 1], bh[nf >> 1][2 + (nf & 1)]);
        }
        __syncthreads();
        if (i + 2 < nch) LOADST(i & 1, i + 2);
        CPCOMMIT;
    }
#undef LOADST

    // epilogue
    #pragma unroll
    for (int mf = 0; mf < 2; mf++)
        #pragma unroll
        for (int nf = 0; nf < 4; nf++) {
            int m = m0 + wm * 32 + mf * 16 + (lane >> 2);
            int n = n0 + wn * 32 + nf * 8 + (lane & 3) * 2;
            float2 v0 = make_float2(acc[mf][nf][0], acc[mf][nf][1]);
            float2 v1 = make_float2(acc[mf][nf][2], acc[mf][nf][3]);
            *(float2*)&Cz[(size_t)m * N + n] = v0;
            *(float2*)&Cz[(size_t)(m + 8) * N + n] = v1;
        }
}

// ---------------- split-K reduce (4 slices of B*512 f32) --------------------
__global__ void reduce4(const float* __restrict__ p, float* __restrict__ o) {
    int i = blockIdx.x * 256 + threadIdx.x;   // over (BB*512)/4
    const size_t n = (size_t)BB * 512;
    float4 a = ((const float4*)p)[i];
    float4 b = ((const float4*)(p + n))[i];
    float4 c = ((const float4*)(p + 2 * n))[i];
    float4 d = ((const float4*)(p + 3 * n))[i];
    ((float4*)o)[i] = make_float4(a.x + b.x + c.x + d.x, a.y + b.y + c.y + d.y,
                                  a.z + b.z + c.z + d.z, a.w + b.w + c.w + d.w);
}

// ===================== prep kernels =========================================
__global__ void split_f32(const float* __restrict__ x, __nv_bfloat16* __restrict__ h,
                          __nv_bfloat16* __restrict__ l, int n4) {
    int i = blockIdx.x * blockDim.x + threadIdx.x;
    if (i >= n4) return;
    float4 v = ((const float4*)x)[i];
    __nv_bfloat16 h0, l0, h1, l1, h2, l2, h3, l3;
    split_bf16(v.x, h0, l0); split_bf16(v.y, h1, l1);
    split_bf16(v.z, h2, l2); split_bf16(v.w, h3, l3);
    __nv_bfloat162 ph0; ph0.x = h0; ph0.y = h1;
    __nv_bfloat162 ph1; ph1.x = h2; ph1.y = h3;
    __nv_bfloat162 pl0; pl0.x = l0; pl0.y = l1;
    __nv_bfloat162 pl1; pl1.x = l2; pl1.y = l3;
    ((__nv_bfloat162*)h)[i * 2] = ph0; ((__nv_bfloat162*)h)[i * 2 + 1] = ph1;
    ((__nv_bfloat162*)l)[i * 2] = pl0; ((__nv_bfloat162*)l)[i * 2 + 1] = pl1;
}

// W[K][N] f32 -> T[N][K] bf16 hi/lo. block(32,8), grid(K/32, N/32)
__global__ void trans_split(const float* __restrict__ W, int K, int N,
                            __nv_bfloat16* __restrict__ Th, __nv_bfloat16* __restrict__ Tl) {
    __shared__ float t[32][33];
    int k0 = blockIdx.x * 32, n0 = blockIdx.y * 32;
    int tx = threadIdx.x, ty = threadIdx.y;
    #pragma unroll
    for (int i = 0; i < 4; i++)
        t[ty + i * 8][tx] = W[(size_t)(k0 + ty + i * 8) * N + n0 + tx];
    __syncthreads();
    #pragma unroll
    for (int i = 0; i < 4; i++) {
        float v = t[tx][ty + i * 8];
        __nv_bfloat16 h, l; split_bf16(v, h, l);
        size_t o = (size_t)(n0 + ty + i * 8) * K + k0 + tx;
        Th[o] = h; Tl[o] = l;
    }
}

// concat [v_W_rgb | q_W_rgb] (8192x256 each) -> T[512][8192] bf16 hi/lo
__global__ void trans_split_rgb(const float* __restrict__ vW, const float* __restrict__ qW,
                                __nv_bfloat16* __restrict__ Th, __nv_bfloat16* __restrict__ Tl) {
    __shared__ float t[32][33];
    int k0 = blockIdx.x * 32, n0 = blockIdx.y * 32;
    int tx = threadIdx.x, ty = threadIdx.y;
    const float* src = (n0 < 256) ? vW : qW;
    int nb = (n0 < 256) ? n0 : (n0 - 256);
    #pragma unroll
    for (int i = 0; i < 4; i++)
        t[ty + i * 8][tx] = src[(size_t)(k0 + ty + i * 8) * 256 + nb + tx];
    __syncthreads();
    #pragma unroll
    for (int i = 0; i < 4; i++) {
        float v = t[tx][ty + i * 8];
        __nv_bfloat16 h, l; split_bf16(v, h, l);
        size_t o = (size_t)(n0 + ty + i * 8) * REPRK + k0 + tx;
        Th[o] = h; Tl[o] = l;
    }
}

// ===================== activation kernels ===================================
__global__ void ln_tanh_rgb(const float* __restrict__ pre,
                            const float* __restrict__ vg, const float* __restrict__ vb,
                            const float* __restrict__ qg, const float* __restrict__ qb,
                            __nv_bfloat16* __restrict__ xvh, __nv_bfloat16* __restrict__ xvl,
                            __nv_bfloat16* __restrict__ xqh, __nv_bfloat16* __restrict__ xql) {
    int b = blockIdx.x, hsel = blockIdx.y, j = threadIdx.x;
    float x = pre[(size_t)b * 512 + hsel * 256 + j];
    float2 r = blockReduce2_256(make_float2(x, x * x));
    float mu = r.x * (1.f / 256.f);
    float inv = rsqrtf(r.y * (1.f / 256.f) - mu * mu + 1e-5f);
    const float* g  = hsel ? qg : vg;
    const float* be = hsel ? qb : vb;
    float y = tanhf((x - mu) * inv * g[j] + be[j]);
    __nv_bfloat16 h, l; split_bf16(y, h, l);
    if (hsel) { xqh[(size_t)b * 512 + j] = h; xql[(size_t)b * 512 + j] = l; }
    else      { xvh[(size_t)b * 512 + j] = h; xvl[(size_t)b * 512 + j] = l; }
}

__global__ void low_kernel(const float* __restrict__ low,
                           const float* __restrict__ vW, const float* __restrict__ vg, const float* __restrict__ vb,
                           const float* __restrict__ qW, const float* __restrict__ qg, const float* __restrict__ qb,
                           __nv_bfloat16* __restrict__ xvh, __nv_bfloat16* __restrict__ xvl,
                           __nv_bfloat16* __restrict__ xqh, __nv_bfloat16* __restrict__ xql) {
    int b = blockIdx.x, j = threadIdx.x;
    __shared__ float lo[32];
    if (j < 32) lo[j] = low[b * 32 + j];
    __syncthreads();
    float sv = 0.f, sq = 0.f;
    #pragma unroll 8
    for (int k = 0; k < 32; k++) {
        float l = lo[k];
        sv += l * vW[k * 256 + j];
        sq += l * qW[k * 256 + j];
    }
    float2 rv = blockReduce2_256(make_float2(sv, sv * sv));
    float muv = rv.x * (1.f / 256.f);
    float iv  = rsqrtf(rv.y * (1.f / 256.f) - muv * muv + 1e-5f);
    float yv = tanhf((sv - muv) * iv * vg[j] + vb[j]);
    __nv_bfloat16 h, l; split_bf16(yv, h, l);
    xvh[(size_t)b * 512 + 256 + j] = h; xvl[(size_t)b * 512 + 256 + j] = l;
    float2 rq = blockReduce2_256(make_float2(sq, sq * sq));
    float muq = rq.x * (1.f / 256.f);
    float iq  = rsqrtf(rq.y * (1.f / 256.f) - muq * muq + 1e-5f);
    float yq = tanhf((sq - muq) * iq * qg[j] + qb[j]);
    split_bf16(yq, h, l);
    xqh[(size_t)b * 512 + 256 + j] = h; xql[(size_t)b * 512 + 256 + j] = l;
}

__global__ void act_kernel(const int* __restrict__ cat, float* __restrict__ act) {
    int b = blockIdx.x * blockDim.x + threadIdx.x;
    if (b >= BB) return;
    float mids[3][8];
    #pragma unroll
    for (int d = 0; d < 8; d++) {
        float lowv = -1.f, width = 2.f;
        #pragma unroll
        for (int l = 0; l < 3; l++) {
            float w = width * (1.f / 16.f);
            float c = (float)cat[(b * 3 + l) * 8 + d];
            float nl = lowv + c * w;
            mids[l][d] = nl + 0.5f * w;
            lowv = nl; width = w;
        }
    }
    #pragma unroll
    for (int k = 0; k < 24; k++) {
        int ls = k >> 3, ds = k & 7;
        #pragma unroll
        for (int d = 0; d < 8; d++) {
            int lvl = ls + (d < ds ? 1 : 0);
            act[((size_t)b * 24 + k) * 8 + d] = (lvl == 0) ? 0.f : mids[lvl - 1][d];
        }
    }
}

__global__ void ln_silu_512_split(const float* __restrict__ pre, const float* __restrict__ g,
                                  const float* __restrict__ be,
                                  __nv_bfloat16* __restrict__ oh, __nv_bfloat16* __restrict__ ol) {
    size_t row = blockIdx.x;
    int j = threadIdx.x;
    float x0 = pre[row * 512 + j];
    float x1 = pre[row * 512 + 256 + j];
    float2 r = blockReduce2_256(make_float2(x0 + x1, x0 * x0 + x1 * x1));
    float mu = r.x * (1.f / 512.f);
    float inv = rsqrtf(r.y * (1.f / 512.f) - mu * mu + 1e-5f);
    float z0 = (x0 - mu) * inv * g[j] + be[j];
    float z1 = (x1 - mu) * inv * g[j + 256] + be[j + 256];
    float y0 = z0 / (1.f + expf(-z0));
    float y1 = z1 / (1.f + expf(-z1));
    __nv_bfloat16 h, l;
    split_bf16(y0, h, l); oh[row * 512 + j] = h;       ol[row * 512 + j] = l;
    split_bf16(y1, h, l); oh[row * 512 + 256 + j] = h; ol[row * 512 + 256 + j] = l;
}

__global__ void ln_silu_512_f32(const float* __restrict__ pre, const float* __restrict__ g,
                                const float* __restrict__ be, float* __restrict__ out) {
    size_t row = blockIdx.x;
    int j = threadIdx.x;
    float x0 = pre[row * 512 + j];
    float x1 = pre[row * 512 + 256 + j];
    float2 r = blockReduce2_256(make_float2(x0 + x1, x0 * x0 + x1 * x1));
    float mu = r.x * (1.f / 512.f);
    float inv = rsqrtf(r.y * (1.f / 512.f) - mu * mu + 1e-5f);
    float z0 = (x0 - mu) * inv * g[j] + be[j];
    float z1 = (x1 - mu) * inv * g[j + 256] + be[j + 256];
    out[row * 512 + j]       = z0 / (1.f + expf(-z0));
    out[row * 512 + 256 + j] = z1 / (1.f + expf(-z1));
}

__global__ void q1_kernel(const float* __restrict__ qbase, const float* __restrict__ act,
                          const float* __restrict__ qW1, const float* __restrict__ g,
                          const float* __restrict__ be,
                          __nv_bfloat16* __restrict__ oh, __nv_bfloat16* __restrict__ ol) {
    size_t idx = blockIdx.x;           // b*24 + s
    int b = (int)(idx / 24);
    int j = threadIdx.x;
    __shared__ float a[8];
    if (j < 8) a[j] = act[idx * 8 + j];
    __syncthreads();
    float x0 = qbase[(size_t)b * 512 + j];
    float x1 = qbase[(size_t)b * 512 + 256 + j];
    #pragma unroll
    for (int d = 0; d < 8; d++) {
        float av = a[d];
        x0 += av * qW1[(size_t)(512 + d) * 512 + j];
        x1 += av * qW1[(size_t)(512 + d) * 512 + 256 + j];
    }
    float2 r = blockReduce2_256(make_float2(x0 + x1, x0 * x0 + x1 * x1));
    float mu = r.x * (1.f / 512.f);
    float inv = rsqrtf(r.y * (1.f / 512.f) - mu * mu + 1e-5f);
    float z0 = (x0 - mu) * inv * g[j] + be[j];
    float z1 = (x1 - mu) * inv * g[j + 256] + be[j + 256];
    float y0 = z0 / (1.f + expf(-z0));
    float y1 = z1 / (1.f + expf(-z1));
    __nv_bfloat16 h, l;
    split_bf16(y0, h, l); oh[idx * 512 + j] = h;       ol[idx * 512 + j] = l;
    split_bf16(y1, h, l); oh[idx * 512 + 256 + j] = h; ol[idx * 512 + 256 + j] = l;
}

__global__ void vhead(const float* __restrict__ v2, const float* __restrict__ Wh,
                      const float* __restrict__ bh, float* __restrict__ out) {
    int b = blockIdx.x, j = threadIdx.x;
    float s = v2[(size_t)b * 512 + j] * Wh[j] + v2[(size_t)b * 512 + 256 + j] * Wh[256 + j];
    float2 r = blockReduce2_256(make_float2(s, 0.f));
    if (j == 0) out[b] = r.x + bh[0];
}

__global__ void qhead(const float* __restrict__ A, const float* __restrict__ Wh,
                      const float* __restrict__ bh, float* __restrict__ out) {
    __shared__ float Ws[512][16];
    int s = blockIdx.y, mb = blockIdx.x, t = threadIdx.x;
    #pragma unroll
    for (int i = 0; i < 32; i++) {
        int idx = t + i * 256;
        int k = idx >> 4, v = idx & 15;
        Ws[k][v] = Wh[(size_t)k * SBH + s * 16 + v];
    }
    __syncthreads();
    int r = t >> 2, cg = t & 3;
    int b = mb * 64 + r;
    const float4* Ap = (const float4*)(A + ((size_t)b * 24 + s) * 512);
    float acc0 = 0.f, acc1 = 0.f, acc2 = 0.f, acc3 = 0.f;
    #pragma unroll 4
    for (int k4 = 0; k4 < 128; k4++) {
        float4 a = Ap[k4];
        int k = k4 * 4;
        float4 w;
        w = *(const float4*)&Ws[k + 0][cg * 4];
        acc0 += a.x * w.x; acc1 += a.x * w.y; acc2 += a.x * w.z; acc3 += a.x * w.w;
        w = *(const float4*)&Ws[k + 1][cg * 4];
        acc0 += a.y * w.x; acc1 += a.y * w.y; acc2 += a.y * w.z; acc3 += a.y * w.w;
        w = *(const float4*)&Ws[k + 2][cg * 4];
        acc0 += a.z * w.x; acc1 += a.z * w.y; acc2 += a.z * w.z; acc3 += a.z * w.w;
        w = *(const float4*)&Ws[k + 3][cg * 4];
        acc0 += a.w * w.x; acc1 += a.w * w.y; acc2 += a.w * w.z; acc3 += a.w * w.w;
    }
    size_t o = (size_t)b * SBH + s * 16 + cg * 4;
    int c0 = s * 16 + cg * 4;
    out[o + 0] = acc0 + bh[c0 + 0];
    out[o + 1] = acc1 + bh[c0 + 1];
    out[o + 2] = acc2 + bh[c0 + 2];
    out[o + 3] = acc3 + bh[c0 + 3];
}

// ===================== launch ================================================
#define GEMM_DSMEM 65536

extern "C" void kernel_launch(void* const* d_in, const int* in_sizes, int n_in,
                              void* d_out, int out_size) {
    const float* rgb_obs = (const float*)d_in[0];
    const float* low_obs = (const float*)d_in[1];
    const int*   category = (const int*)d_in[2];
    const float* v_W_rgb = (const float*)d_in[3];
    const float* v_g_rgb = (const float*)d_in[4];
    const float* v_b_rgb = (const float*)d_in[5];
    const float* v_W_low = (const float*)d_in[6];
    const float* v_g_low = (const float*)d_in[7];
    const float* v_b_low = (const float*)d_in[8];
    const float* v_W1 = (const float*)d_in[9];
    const float* v_g1 = (const float*)d_in[10];
    const float* v_b1 = (const float*)d_in[11];
    const float* v_W2 = (const float*)d_in[12];
    const float* v_g2 = (const float*)d_in[13];
    const float* v_b2 = (const float*)d_in[14];
    const float* v_Wh = (const float*)d_in[15];
    const float* v_bh = (const float*)d_in[16];
    const float* q_W_rgb = (const float*)d_in[17];
    const float* q_g_rgb = (const float*)d_in[18];
    const float* q_b_rgb = (const float*)d_in[19];
    const float* q_W_low = (const float*)d_in[20];
    const float* q_g_low = (const float*)d_in[21];
    const float* q_b_low = (const float*)d_in[22];
    const float* q_W1 = (const float*)d_in[23];
    const float* q_g1 = (const float*)d_in[24];
    const float* q_b1 = (const float*)d_in[25];
    const float* q_W2 = (const float*)d_in[26];
    const float* q_g2 = (const float*)d_in[27];
    const float* q_b2 = (const float*)d_in[28];
    const float* q_Wh = (const float*)d_in[29];
    const float* q_bh = (const float*)d_in[30];

    float* out_value = (float*)d_out;
    float* out_adv   = out_value + BB;

    cudaFuncSetAttribute(gemm_mma3, cudaFuncAttributeMaxDynamicSharedMemorySize, GEMM_DSMEM);

    __nv_bfloat16 *Ahi, *Alo, *WrgbTh, *WrgbTl, *xvh, *xvl, *xqh, *xql;
    __nv_bfloat16 *vW1Th, *vW1Tl, *vW2Th, *vW2Tl, *qW1Th, *qW1Tl, *qW2Th, *qW2Tl;
    __nv_bfloat16 *t1h, *t1l, *q1h, *q1l;
    float *rgb_part, *rgb_pre, *t0, *t1f, *qbase, *act, *q2pre, *q2f;
    cudaGetSymbolAddress((void**)&Ahi, g_Ahi);       cudaGetSymbolAddress((void**)&Alo, g_Alo);
    cudaGetSymbolAddress((void**)&WrgbTh, g_WrgbTh); cudaGetSymbolAddress((void**)&WrgbTl, g_WrgbTl);
    cudaGetSymbolAddress((void**)&rgb_part, g_rgb_part);
    cudaGetSymbolAddress((void**)&rgb_pre, g_rgb_pre);
    cudaGetSymbolAddress((void**)&xvh, g_xvh); cudaGetSymbolAddress((void**)&xvl, g_xvl);
    cudaGetSymbolAddress((void**)&xqh, g_xqh); cudaGetSymbolAddress((void**)&xql, g_xql);
    cudaGetSymbolAddress((void**)&vW1Th, g_vW1Th); cudaGetSymbolAddress((void**)&vW1Tl, g_vW1Tl);
    cudaGetSymbolAddress((void**)&vW2Th, g_vW2Th); cudaGetSymbolAddress((void**)&vW2Tl, g_vW2Tl);
    cudaGetSymbolAddress((void**)&qW1Th, g_qW1Th); cudaGetSymbolAddress((void**)&qW1Tl, g_qW1Tl);
    cudaGetSymbolAddress((void**)&qW2Th, g_qW2Th); cudaGetSymbolAddress((void**)&qW2Tl, g_qW2Tl);
    cudaGetSymbolAddress((void**)&t0, g_t0);
    cudaGetSymbolAddress((void**)&t1h, g_t1h); cudaGetSymbolAddress((void**)&t1l, g_t1l);
    cudaGetSymbolAddress((void**)&t1f, g_t1f);
    cudaGetSymbolAddress((void**)&qbase, g_qbase);
    cudaGetSymbolAddress((void**)&act, g_act);
    cudaGetSymbolAddress((void**)&q1h, g_q1h); cudaGetSymbolAddress((void**)&q1l, g_q1l);
    cudaGetSymbolAddress((void**)&q2pre, g_q2pre);
    cudaGetSymbolAddress((void**)&q2f, g_q2f);

    // ---- prep ----
    split_f32<<<(BB * REPRK / 4 + 255) / 256, 256>>>(rgb_obs, Ahi, Alo, BB * REPRK / 4);
    trans_split_rgb<<<dim3(REPRK / 32, 512 / 32), dim3(32, 8)>>>(v_W_rgb, q_W_rgb, WrgbTh, WrgbTl);
    trans_split<<<dim3(16, 16), dim3(32, 8)>>>(v_W1, 512, 512, vW1Th, vW1Tl);
    trans_split<<<dim3(16, 16), dim3(32, 8)>>>(v_W2, 512, 512, vW2Th, vW2Tl);
    trans_split<<<dim3(16, 16), dim3(32, 8)>>>(q_W1, 512, 512, qW1Th, qW1Tl);  // first 512 rows
    trans_split<<<dim3(16, 16), dim3(32, 8)>>>(q_W2, 512, 512, qW2Th, qW2Tl);
    act_kernel<<<(BB + 127) / 128, 128>>>(category, act);

    // ---- shared rgb features: split-K=4 over K=8192 ----
    gemm_mma3<<<dim3(4, BB / 128, 4), 512, GEMM_DSMEM>>>(Ahi, Alo, WrgbTh, WrgbTl,
                                                         rgb_part, BB, 512, 2048, REPRK);
    reduce4<<<(BB * 512 / 4) / 256, 256>>>(rgb_part, rgb_pre);
    ln_tanh_rgb<<<dim3(BB, 2), 256>>>(rgb_pre, v_g_rgb, v_b_rgb, q_g_rgb, q_b_rgb, xvh, xvl, xqh, xql);
    low_kernel<<<BB, 256>>>(low_obs, v_W_low, v_g_low, v_b_low, q_W_low, q_g_low, q_b_low,
                            xvh, xvl, xqh, xql);

    // ---- value path ----
    gemm_mma3<<<dim3(4, BB / 128, 1), 512, GEMM_DSMEM>>>(xvh, xvl, vW1Th, vW1Tl, t0, BB, 512, 512, 512);
    ln_silu_512_split<<<BB, 256>>>(t0, v_g1, v_b1, t1h, t1l);
    gemm_mma3<<<dim3(4, BB / 128, 1), 512, GEMM_DSMEM>>>(t1h, t1l, vW2Th, vW2Tl, t0, BB, 512, 512, 512);
    ln_silu_512_f32<<<BB, 256>>>(t0, v_g2, v_b2, t1f);
    vhead<<<BB, 256>>>(t1f, v_Wh, v_bh, out_value);

    // ---- q path ----
    gemm_mma3<<<dim3(4, BB / 128, 1), 512, GEMM_DSMEM>>>(xqh, xql, qW1Th, qW1Tl, qbase, BB, 512, 512, 512);
    q1_kernel<<<BB * SS, 256>>>(qbase, act, q_W1, q_g1, q_b1, q1h, q1l);
    gemm_mma3<<<dim3(4, (BB * SS) / 128, 1), 512, GEMM_DSMEM>>>(q1h, q1l, qW2Th, qW2Tl,
                                                                q2pre, BB * SS, 512, 512, 512);
    ln_silu_512_f32<<<BB * SS, 256>>>(q2pre, q_g2, q_b2, q2f);
    qhead<<<dim3(BB / 64, SS), 256>>>(q2f, q_Wh, q_bh, out_adv);
}